// round 9
// baseline (speedup 1.0000x reference)
#include <cuda_runtime.h>
#include <cuda_fp16.h>
#include <mma.h>

using namespace nvcuda;

#define BATCH 2
#define SEQ   2048
#define DIMSZ 1024
#define HEADS 16
#define HD    64
#define ROWS  (BATCH*SEQ)   // 4096

// Only tiny scratch: last 128 rows of A, so the final cascade launch never
// reads memory it is overwriting. 256 KB — fits the driver's default heap.
__device__ __half g_tail[128 * DIMSZ];

// ---------------- projection GEMM: C[2048,1024] = X@W^T + bias (half out) ----------------
#define BM 128
#define BN 128
#define BK 32
#define LDT 40

__global__ __launch_bounds__(256) void gemm_proj(
    const float* __restrict__ X, const float* __restrict__ W,
    const float* __restrict__ bias, __half* __restrict__ Cout)
{
    constexpr int K = DIMSZ, NC = DIMSZ;
    __shared__ __half As[BM * LDT];
    __shared__ __half Bs[BN * LDT];
    __shared__ float  stage[8][256];

    const int tid = threadIdx.x;
    const int w = tid >> 5, lane = tid & 31;
    const int wm = w & 1, wn = w >> 1;
    const int m0 = blockIdx.y * BM, n0 = blockIdx.x * BN;

    wmma::fragment<wmma::accumulator, 16, 16, 16, float> acc[4][2];
#pragma unroll
    for (int mi = 0; mi < 4; mi++)
#pragma unroll
        for (int ni = 0; ni < 2; ni++) wmma::fill_fragment(acc[mi][ni], 0.0f);

    for (int k0 = 0; k0 < K; k0 += BK) {
#pragma unroll
        for (int it = 0; it < 4; it++) {
            int idx = tid + it * 256;
            int row = idx >> 3, cv = (idx & 7) * 4;
            float4 v = *reinterpret_cast<const float4*>(&X[(size_t)(m0 + row) * K + k0 + cv]);
            __half* dst = &As[row * LDT + cv];
            *reinterpret_cast<__half2*>(dst)     = __floats2half2_rn(v.x, v.y);
            *reinterpret_cast<__half2*>(dst + 2) = __floats2half2_rn(v.z, v.w);
        }
#pragma unroll
        for (int it = 0; it < 4; it++) {
            int idx = tid + it * 256;
            int row = idx >> 3, cv = (idx & 7) * 4;
            float4 v = *reinterpret_cast<const float4*>(&W[(size_t)(n0 + row) * K + k0 + cv]);
            __half* dst = &Bs[row * LDT + cv];
            *reinterpret_cast<__half2*>(dst)     = __floats2half2_rn(v.x, v.y);
            *reinterpret_cast<__half2*>(dst + 2) = __floats2half2_rn(v.z, v.w);
        }
        __syncthreads();
#pragma unroll
        for (int kk = 0; kk < BK; kk += 16) {
            wmma::fragment<wmma::matrix_a, 16, 16, 16, __half, wmma::row_major> af[4];
            wmma::fragment<wmma::matrix_b, 16, 16, 16, __half, wmma::col_major> bf[2];
#pragma unroll
            for (int mi = 0; mi < 4; mi++)
                wmma::load_matrix_sync(af[mi], &As[(wm * 64 + mi * 16) * LDT + kk], LDT);
#pragma unroll
            for (int ni = 0; ni < 2; ni++)
                wmma::load_matrix_sync(bf[ni], &Bs[(wn * 32 + ni * 16) * LDT + kk], LDT);
#pragma unroll
            for (int mi = 0; mi < 4; mi++)
#pragma unroll
                for (int ni = 0; ni < 2; ni++)
                    wmma::mma_sync(acc[mi][ni], af[mi], bf[ni], acc[mi][ni]);
        }
        __syncthreads();
    }
#pragma unroll
    for (int mi = 0; mi < 4; mi++)
#pragma unroll
        for (int ni = 0; ni < 2; ni++) {
            wmma::store_matrix_sync(&stage[w][0], acc[mi][ni], 16, wmma::mem_row_major);
            __syncwarp();
            int grow0 = m0 + wm * 64 + mi * 16;
            int gcol0 = n0 + wn * 32 + ni * 16;
#pragma unroll
            for (int e = lane; e < 256; e += 32) {
                int r = e >> 4, c = e & 15;
                Cout[(size_t)(grow0 + r) * NC + gcol0 + c] =
                    __float2half(stage[w][e] + bias[gcol0 + c]);
            }
            __syncwarp();
        }
}

// ---------------- attention: Q on-the-fly, flash loop, A -> d_out[8:16MB] ----------------
#define QTILE 128
#define KTILE 64
#define LQH 72
#define LSF 68
#define ATT_SMEM ((QTILE*LQH + 2*KTILE*LQH + QTILE*LQH) * 2 + (2 * QTILE * LSF) * 4)

__global__ __launch_bounds__(128) void attn_kernel(
    const float* __restrict__ query, const float* __restrict__ Wq,
    const float* __restrict__ bq, __half* dbase, int b)
{
    const __half* Kp = dbase;                        // [0:4MB)  batch-local rows
    const __half* Vp = dbase + 2 * 1024 * 1024;      // [4:8MB)
    __half* Ap       = dbase + 4 * 1024 * 1024;      // [8:16MB), global rows

    extern __shared__ char smem[];
    __half* sQ = reinterpret_cast<__half*>(smem);
    __half* sK = sQ + QTILE * LQH;
    __half* sV = sK + KTILE * LQH;
    __half* sP = sV + KTILE * LQH;
    float*  sS = reinterpret_cast<float*>(sP + QTILE * LQH);
    float*  sO = sS + QTILE * LSF;

    const int tid = threadIdx.x;
    const int w = tid >> 5;
    const int h = blockIdx.y;
    const int q0 = blockIdx.x * QTILE;
    const int col0 = h * HD;
    const int row0 = w * 32;

    // ---- Phase 0: Q tile = (query_b @ Wq_h^T + bq) * 0.125, into sQ ----
    {
        wmma::fragment<wmma::accumulator, 16, 16, 16, float> qacc[2][4];
#pragma unroll
        for (int mi = 0; mi < 2; mi++)
#pragma unroll
            for (int ni = 0; ni < 4; ni++) wmma::fill_fragment(qacc[mi][ni], 0.0f);

        for (int k0 = 0; k0 < DIMSZ; k0 += 64) {
            // query chunk [128 x 64] fp32 -> half into sP
            for (int i = tid; i < 128 * 16; i += 128) {
                int row = i >> 4, cv = (i & 15) * 4;
                float4 v = *reinterpret_cast<const float4*>(
                    &query[(size_t)(b * SEQ + q0 + row) * DIMSZ + k0 + cv]);
                __half* dst = &sP[row * LQH + cv];
                *reinterpret_cast<__half2*>(dst)     = __floats2half2_rn(v.x, v.y);
                *reinterpret_cast<__half2*>(dst + 2) = __floats2half2_rn(v.z, v.w);
            }
            // Wq chunk [64 x 64] fp32 -> half into sK
            for (int i = tid; i < 64 * 16; i += 128) {
                int row = i >> 4, cv = (i & 15) * 4;
                float4 v = *reinterpret_cast<const float4*>(
                    &Wq[(size_t)(col0 + row) * DIMSZ + k0 + cv]);
                __half* dst = &sK[row * LQH + cv];
                *reinterpret_cast<__half2*>(dst)     = __floats2half2_rn(v.x, v.y);
                *reinterpret_cast<__half2*>(dst + 2) = __floats2half2_rn(v.z, v.w);
            }
            __syncthreads();
#pragma unroll
            for (int kk = 0; kk < 64; kk += 16) {
                wmma::fragment<wmma::matrix_a, 16, 16, 16, __half, wmma::row_major> af[2];
                wmma::fragment<wmma::matrix_b, 16, 16, 16, __half, wmma::col_major> bf[4];
#pragma unroll
                for (int mi = 0; mi < 2; mi++)
                    wmma::load_matrix_sync(af[mi], &sP[(row0 + mi * 16) * LQH + kk], LQH);
#pragma unroll
                for (int ni = 0; ni < 4; ni++)
                    wmma::load_matrix_sync(bf[ni], &sK[(ni * 16) * LQH + kk], LQH);
#pragma unroll
                for (int mi = 0; mi < 2; mi++)
#pragma unroll
                    for (int ni = 0; ni < 4; ni++)
                        wmma::mma_sync(qacc[mi][ni], af[mi], bf[ni], qacc[mi][ni]);
            }
            __syncthreads();
        }
#pragma unroll
        for (int mi = 0; mi < 2; mi++)
#pragma unroll
            for (int ni = 0; ni < 4; ni++)
                wmma::store_matrix_sync(&sS[(row0 + mi * 16) * LSF + ni * 16],
                                        qacc[mi][ni], LSF, wmma::mem_row_major);
        __syncthreads();
        {
            int r = tid;
#pragma unroll
            for (int c = 0; c < HD; c++)
                sQ[r * LQH + c] = __float2half((sS[r * LSF + c] + bq[col0 + c]) * 0.125f);
        }
        __syncthreads();
    }

    // init O accumulator
    {
        int r = tid;
#pragma unroll
        for (int d = 0; d < HD; d += 4)
            *reinterpret_cast<float4*>(&sO[r * LSF + d]) = make_float4(0.f, 0.f, 0.f, 0.f);
    }
    float m = -1e30f, l = 0.0f;

    for (int t = 0; t < SEQ / KTILE; t++) {
        const int j0 = t * KTILE;
        __syncthreads();
        for (int i = tid; i < KTILE * 8; i += 128) {
            int row = i >> 3, cv = (i & 7) * 8;
            *reinterpret_cast<float4*>(&sK[row * LQH + cv]) =
                *reinterpret_cast<const float4*>(&Kp[(size_t)(j0 + row) * DIMSZ + col0 + cv]);
            *reinterpret_cast<float4*>(&sV[row * LQH + cv]) =
                *reinterpret_cast<const float4*>(&Vp[(size_t)(j0 + row) * DIMSZ + col0 + cv]);
        }
        __syncthreads();

        // S = Q @ K^T (scale pre-folded into Q)
        {
            wmma::fragment<wmma::accumulator, 16, 16, 16, float> sacc[2][4];
#pragma unroll
            for (int mi = 0; mi < 2; mi++)
#pragma unroll
                for (int ni = 0; ni < 4; ni++) wmma::fill_fragment(sacc[mi][ni], 0.0f);
#pragma unroll
            for (int kk = 0; kk < HD; kk += 16) {
                wmma::fragment<wmma::matrix_a, 16, 16, 16, __half, wmma::row_major> af[2];
                wmma::fragment<wmma::matrix_b, 16, 16, 16, __half, wmma::col_major> bf[4];
#pragma unroll
                for (int mi = 0; mi < 2; mi++)
                    wmma::load_matrix_sync(af[mi], &sQ[(row0 + mi * 16) * LQH + kk], LQH);
#pragma unroll
                for (int ni = 0; ni < 4; ni++)
                    wmma::load_matrix_sync(bf[ni], &sK[(ni * 16) * LQH + kk], LQH);
#pragma unroll
                for (int mi = 0; mi < 2; mi++)
#pragma unroll
                    for (int ni = 0; ni < 4; ni++)
                        wmma::mma_sync(sacc[mi][ni], af[mi], bf[ni], sacc[mi][ni]);
            }
#pragma unroll
            for (int mi = 0; mi < 2; mi++)
#pragma unroll
                for (int ni = 0; ni < 4; ni++)
                    wmma::store_matrix_sync(&sS[(row0 + mi * 16) * LSF + ni * 16],
                                            sacc[mi][ni], LSF, wmma::mem_row_major);
        }
        __syncthreads();

        // online softmax, one row per thread
        {
            int r = tid;
            float tmax = -1e30f;
#pragma unroll
            for (int j = 0; j < KTILE; j++) tmax = fmaxf(tmax, sS[r * LSF + j]);
            float m_new = fmaxf(m, tmax);
            float alpha = __expf(m - m_new);
            float sum = 0.0f;
#pragma unroll
            for (int j = 0; j < KTILE; j++) {
                float p = __expf(sS[r * LSF + j] - m_new);
                sum += p;
                sP[r * LQH + j] = __float2half(p);
            }
            l = l * alpha + sum;
            m = m_new;
#pragma unroll
            for (int d = 0; d < HD; d += 4) {
                float4 o = *reinterpret_cast<float4*>(&sO[r * LSF + d]);
                o.x *= alpha; o.y *= alpha; o.z *= alpha; o.w *= alpha;
                *reinterpret_cast<float4*>(&sO[r * LSF + d]) = o;
            }
        }
        __syncthreads();

        // O += P @ V
        {
            wmma::fragment<wmma::accumulator, 16, 16, 16, float> oacc[2][4];
#pragma unroll
            for (int mi = 0; mi < 2; mi++)
#pragma unroll
                for (int ni = 0; ni < 4; ni++)
                    wmma::load_matrix_sync(oacc[mi][ni],
                        &sO[(row0 + mi * 16) * LSF + ni * 16], LSF, wmma::mem_row_major);
#pragma unroll
            for (int kk = 0; kk < KTILE; kk += 16) {
                wmma::fragment<wmma::matrix_a, 16, 16, 16, __half, wmma::row_major> af[2];
                wmma::fragment<wmma::matrix_b, 16, 16, 16, __half, wmma::row_major> bf[4];
#pragma unroll
                for (int mi = 0; mi < 2; mi++)
                    wmma::load_matrix_sync(af[mi], &sP[(row0 + mi * 16) * LQH + kk], LQH);
#pragma unroll
                for (int ni = 0; ni < 4; ni++)
                    wmma::load_matrix_sync(bf[ni], &sV[kk * LQH + ni * 16], LQH);
#pragma unroll
                for (int mi = 0; mi < 2; mi++)
#pragma unroll
                    for (int ni = 0; ni < 4; ni++)
                        wmma::mma_sync(oacc[mi][ni], af[mi], bf[ni], oacc[mi][ni]);
            }
#pragma unroll
            for (int mi = 0; mi < 2; mi++)
#pragma unroll
                for (int ni = 0; ni < 4; ni++)
                    wmma::store_matrix_sync(&sO[(row0 + mi * 16) * LSF + ni * 16],
                                            oacc[mi][ni], LSF, wmma::mem_row_major);
        }
    }
    __syncthreads();

    // write A rows (global row index)
    {
        int r = tid;
        float inv = 1.0f / l;
#pragma unroll
        for (int d = 0; d < HD; d++)
            Ap[(size_t)(b * SEQ + q0 + r) * DIMSZ + col0 + d] =
                __float2half(sO[r * LSF + d] * inv);
    }
}

// ---------------- copy last 128 A rows into g_tail ----------------
__global__ void copy_tail(const __half* __restrict__ src) {
    int i = blockIdx.x * blockDim.x + threadIdx.x;   // 16384 int4 = 256 KB
    reinterpret_cast<int4*>(g_tail)[i] = reinterpret_cast<const int4*>(src)[i];
}

// ---------------- cascaded output GEMM: out[row0..] = A@Wo^T + bo ----------------
// BM=64, BN=128. Per-launch read/write ranges verified disjoint; the final
// launch (use_tail) reads A rows 3968..4095 from g_tail.
#define OBM 64

__global__ __launch_bounds__(256) void gemm_out(
    const float* __restrict__ W, const float* __restrict__ bias,
    float* __restrict__ out, int row0, int use_tail)
{
    constexpr int K = DIMSZ, NC = DIMSZ;
    const __half* A = use_tail ? g_tail
                               : reinterpret_cast<const __half*>(out) + 4 * 1024 * 1024;
    const int abase = use_tail ? 3968 : 0;

    __shared__ __half As[OBM * LDT];
    __shared__ __half Bs[BN * LDT];
    __shared__ float  stage[8][256];

    const int tid = threadIdx.x;
    const int w = tid >> 5, lane = tid & 31;
    const int wm = w & 1, wn = w >> 1;   // 2x32 rows, 4x32 cols
    const int m0 = row0 + blockIdx.y * OBM;
    const int n0 = blockIdx.x * BN;

    wmma::fragment<wmma::accumulator, 16, 16, 16, float> acc[2][2];
#pragma unroll
    for (int mi = 0; mi < 2; mi++)
#pragma unroll
        for (int ni = 0; ni < 2; ni++) wmma::fill_fragment(acc[mi][ni], 0.0f);

    for (int k0 = 0; k0 < K; k0 += BK) {
        // A tile 64x32 half: one float4 (8 halves) per thread
        {
            int row = tid >> 2, cv = (tid & 3) * 8;
            *reinterpret_cast<float4*>(&As[row * LDT + cv]) =
                *reinterpret_cast<const float4*>(&A[(size_t)(m0 + row - abase) * K + k0 + cv]);
        }
        // W tile 128x32 fp32 -> half
#pragma unroll
        for (int it = 0; it < 4; it++) {
            int idx = tid + it * 256;
            int row = idx >> 3, cv = (idx & 7) * 4;
            float4 v = *reinterpret_cast<const float4*>(&W[(size_t)(n0 + row) * K + k0 + cv]);
            __half* dst = &Bs[row * LDT + cv];
            *reinterpret_cast<__half2*>(dst)     = __floats2half2_rn(v.x, v.y);
            *reinterpret_cast<__half2*>(dst + 2) = __floats2half2_rn(v.z, v.w);
        }
        __syncthreads();
#pragma unroll
        for (int kk = 0; kk < BK; kk += 16) {
            wmma::fragment<wmma::matrix_a, 16, 16, 16, __half, wmma::row_major> af[2];
            wmma::fragment<wmma::matrix_b, 16, 16, 16, __half, wmma::col_major> bf[2];
#pragma unroll
            for (int mi = 0; mi < 2; mi++)
                wmma::load_matrix_sync(af[mi], &As[(wm * 32 + mi * 16) * LDT + kk], LDT);
#pragma unroll
            for (int ni = 0; ni < 2; ni++)
                wmma::load_matrix_sync(bf[ni], &Bs[(wn * 32 + ni * 16) * LDT + kk], LDT);
#pragma unroll
            for (int mi = 0; mi < 2; mi++)
#pragma unroll
                for (int ni = 0; ni < 2; ni++)
                    wmma::mma_sync(acc[mi][ni], af[mi], bf[ni], acc[mi][ni]);
        }
        __syncthreads();
    }
#pragma unroll
    for (int mi = 0; mi < 2; mi++)
#pragma unroll
        for (int ni = 0; ni < 2; ni++) {
            wmma::store_matrix_sync(&stage[w][0], acc[mi][ni], 16, wmma::mem_row_major);
            __syncwarp();
            int grow0 = m0 + wm * 32 + mi * 16;
            int gcol0 = n0 + wn * 32 + ni * 16;
#pragma unroll
            for (int e = lane; e < 256; e += 32) {
                int r = e >> 4, c = e & 15;
                out[(size_t)(grow0 + r) * NC + gcol0 + c] = stage[w][e] + bias[gcol0 + c];
            }
            __syncwarp();
        }
}

// ---------------- launch ----------------
extern "C" void kernel_launch(void* const* d_in, const int* in_sizes, int n_in,
                              void* d_out, int out_size) {
    const float* query = (const float*)d_in[0];
    const float* key   = (const float*)d_in[1];
    const float* value = (const float*)d_in[2];
    const float* Wq    = (const float*)d_in[3];
    const float* bq    = (const float*)d_in[4];
    const float* Wk    = (const float*)d_in[5];
    const float* bk    = (const float*)d_in[6];
    const float* Wv    = (const float*)d_in[7];
    const float* bv    = (const float*)d_in[8];
    const float* Wo    = (const float*)d_in[9];
    const float* bo    = (const float*)d_in[10];
    float* out = (float*)d_out;
    __half* dbase = (__half*)d_out;

    cudaFuncSetAttribute(attn_kernel, cudaFuncAttributeMaxDynamicSharedMemorySize, ATT_SMEM);

    dim3 pgrid(DIMSZ / BN, SEQ / BM);            // (8, 16) per-batch projections
    dim3 agrid(SEQ / QTILE, HEADS);              // (16, 16)

    // batch 0: K0,V0 -> [0:8MB); A0 -> [8:12MB)
    gemm_proj<<<pgrid, 256>>>(key,   Wk, bk, dbase);
    gemm_proj<<<pgrid, 256>>>(value, Wv, bv, dbase + 2 * 1024 * 1024);
    attn_kernel<<<agrid, 128, ATT_SMEM>>>(query, Wq, bq, dbase, 0);

    // batch 1: K1,V1 overwrite [0:8MB); A1 -> [12:16MB)
    gemm_proj<<<pgrid, 256>>>(key + (size_t)SEQ * DIMSZ,   Wk, bk, dbase);
    gemm_proj<<<pgrid, 256>>>(value + (size_t)SEQ * DIMSZ, Wv, bv, dbase + 2 * 1024 * 1024);
    attn_kernel<<<agrid, 128, ATT_SMEM>>>(query, Wq, bq, dbase, 1);

    // stash last 128 A rows (cascade's final segment source)
    copy_tail<<<64, 256>>>(dbase + 4 * 1024 * 1024 + (size_t)3968 * DIMSZ);

    // cascaded in-place output GEMM
    const int seg[6] = {0, 2048, 3072, 3584, 3840, 3968};
    for (int i = 0; i < 5; i++) {
        dim3 g(DIMSZ / BN, (seg[i + 1] - seg[i]) / OBM);
        gemm_out<<<g, 256>>>(Wo, bo, out, seg[i], 0);
    }
    gemm_out<<<dim3(DIMSZ / BN, 2), 256>>>(Wo, bo, out, 3968, 1);
}

// round 10
// speedup vs baseline: 1.1380x; 1.1380x over previous
#include <cuda_runtime.h>
#include <cuda_fp16.h>
#include <mma.h>

using namespace nvcuda;

#define BATCH 2
#define SEQ   2048
#define DIMSZ 1024
#define HEADS 16
#define HD    64
#define ROWS  (BATCH*SEQ)   // 4096

// Tiny scratch only (known-safe at 256 KB): last 128 rows of A for the cascade.
__device__ __half g_tail[128 * DIMSZ];

// ---------------- fused K+V projection: z=0 -> K, z=1 -> V ----------------
#define BM 128
#define BN 128
#define BK 32
#define LDT 40

__global__ __launch_bounds__(256) void gemm_proj_kv(
    const float* __restrict__ key, const float* __restrict__ value,
    const float* __restrict__ Wk, const float* __restrict__ bk,
    const float* __restrict__ Wv, const float* __restrict__ bv,
    __half* dstK, __half* dstV)
{
    constexpr int K = DIMSZ, NC = DIMSZ;
    const float* X    = blockIdx.z ? value : key;
    const float* W    = blockIdx.z ? Wv : Wk;
    const float* bias = blockIdx.z ? bv : bk;
    __half* Cout      = blockIdx.z ? dstV : dstK;

    __shared__ __half As[BM * LDT];
    __shared__ __half Bs[BN * LDT];
    __shared__ float  stage[8][256];

    const int tid = threadIdx.x;
    const int w = tid >> 5, lane = tid & 31;
    const int wm = w & 1, wn = w >> 1;
    const int m0 = blockIdx.y * BM, n0 = blockIdx.x * BN;

    wmma::fragment<wmma::accumulator, 16, 16, 16, float> acc[4][2];
#pragma unroll
    for (int mi = 0; mi < 4; mi++)
#pragma unroll
        for (int ni = 0; ni < 2; ni++) wmma::fill_fragment(acc[mi][ni], 0.0f);

    for (int k0 = 0; k0 < K; k0 += BK) {
#pragma unroll
        for (int it = 0; it < 4; it++) {
            int idx = tid + it * 256;
            int row = idx >> 3, cv = (idx & 7) * 4;
            float4 v = *reinterpret_cast<const float4*>(&X[(size_t)(m0 + row) * K + k0 + cv]);
            __half* dst = &As[row * LDT + cv];
            *reinterpret_cast<__half2*>(dst)     = __floats2half2_rn(v.x, v.y);
            *reinterpret_cast<__half2*>(dst + 2) = __floats2half2_rn(v.z, v.w);
        }
#pragma unroll
        for (int it = 0; it < 4; it++) {
            int idx = tid + it * 256;
            int row = idx >> 3, cv = (idx & 7) * 4;
            float4 v = *reinterpret_cast<const float4*>(&W[(size_t)(n0 + row) * K + k0 + cv]);
            __half* dst = &Bs[row * LDT + cv];
            *reinterpret_cast<__half2*>(dst)     = __floats2half2_rn(v.x, v.y);
            *reinterpret_cast<__half2*>(dst + 2) = __floats2half2_rn(v.z, v.w);
        }
        __syncthreads();
#pragma unroll
        for (int kk = 0; kk < BK; kk += 16) {
            wmma::fragment<wmma::matrix_a, 16, 16, 16, __half, wmma::row_major> af[4];
            wmma::fragment<wmma::matrix_b, 16, 16, 16, __half, wmma::col_major> bf[2];
#pragma unroll
            for (int mi = 0; mi < 4; mi++)
                wmma::load_matrix_sync(af[mi], &As[(wm * 64 + mi * 16) * LDT + kk], LDT);
#pragma unroll
            for (int ni = 0; ni < 2; ni++)
                wmma::load_matrix_sync(bf[ni], &Bs[(wn * 32 + ni * 16) * LDT + kk], LDT);
#pragma unroll
            for (int mi = 0; mi < 4; mi++)
#pragma unroll
                for (int ni = 0; ni < 2; ni++)
                    wmma::mma_sync(acc[mi][ni], af[mi], bf[ni], acc[mi][ni]);
        }
        __syncthreads();
    }
#pragma unroll
    for (int mi = 0; mi < 4; mi++)
#pragma unroll
        for (int ni = 0; ni < 2; ni++) {
            wmma::store_matrix_sync(&stage[w][0], acc[mi][ni], 16, wmma::mem_row_major);
            __syncwarp();
            int grow0 = m0 + wm * 64 + mi * 16;
            int gcol0 = n0 + wn * 32 + ni * 16;
#pragma unroll
            for (int e = lane; e < 256; e += 32) {
                int r = e >> 4, c = e & 15;
                Cout[(size_t)(grow0 + r) * NC + gcol0 + c] =
                    __float2half(stage[w][e] + bias[gcol0 + c]);
            }
            __syncwarp();
        }
}

// ---------------- attention: 256 threads, QTILE=128, KTILE=128 ----------------
#define QTILE 128
#define KTILE 128
#define LQH 72    // half stride for 64-col tiles (Q/K/V)
#define LPH 136   // half stride for 128-col P tile
#define LSF 132   // float stride for 128-col S tile
#define LOF 68    // float stride for O accumulator
#define ATT_SMEM (18432 + 18432 + 18432 + 34816 + 67584 + 34816)  // 192512 B

__global__ __launch_bounds__(256, 1) void attn_kernel(
    const float* __restrict__ query, const float* __restrict__ Wq,
    const float* __restrict__ bq, __half* dbase, int b)
{
    const __half* Kp = dbase;
    const __half* Vp = dbase + 2 * 1024 * 1024;
    __half* Ap       = dbase + 4 * 1024 * 1024;

    extern __shared__ char smem[];
    __half* sQ = reinterpret_cast<__half*>(smem);                    // 128x72
    __half* sK = sQ + QTILE * LQH;                                   // 128x72
    __half* sV = sK + KTILE * LQH;                                   // 128x72
    __half* sP = sV + KTILE * LQH;                                   // 128x136
    float*  sS = reinterpret_cast<float*>(sP + QTILE * LPH);         // 128x132
    float*  sO = sS + QTILE * LSF;                                   // 128x68

    const int tid = threadIdx.x;
    const int w = tid >> 5;
    const int h = blockIdx.y;
    const int q0 = blockIdx.x * QTILE;
    const int col0 = h * HD;

    // ---- Phase 0: Q tile = (query_b @ Wq_h^T + bq) * 0.125 -> sQ ----
    {
        const int wm = w >> 1, wn = w & 1;   // 4x2 warps over 128x64
        wmma::fragment<wmma::accumulator, 16, 16, 16, float> qacc[2][2];
#pragma unroll
        for (int mi = 0; mi < 2; mi++)
#pragma unroll
            for (int ni = 0; ni < 2; ni++) wmma::fill_fragment(qacc[mi][ni], 0.0f);

        for (int k0 = 0; k0 < DIMSZ; k0 += 64) {
            for (int i = tid; i < 128 * 16; i += 256) {      // query chunk 128x64 f32->h
                int row = i >> 4, cv = (i & 15) * 4;
                float4 v = *reinterpret_cast<const float4*>(
                    &query[(size_t)(b * SEQ + q0 + row) * DIMSZ + k0 + cv]);
                __half* dst = &sP[row * LQH + cv];
                *reinterpret_cast<__half2*>(dst)     = __floats2half2_rn(v.x, v.y);
                *reinterpret_cast<__half2*>(dst + 2) = __floats2half2_rn(v.z, v.w);
            }
            for (int i = tid; i < 64 * 16; i += 256) {       // Wq chunk 64x64 f32->h
                int row = i >> 4, cv = (i & 15) * 4;
                float4 v = *reinterpret_cast<const float4*>(
                    &Wq[(size_t)(col0 + row) * DIMSZ + k0 + cv]);
                __half* dst = &sK[row * LQH + cv];
                *reinterpret_cast<__half2*>(dst)     = __floats2half2_rn(v.x, v.y);
                *reinterpret_cast<__half2*>(dst + 2) = __floats2half2_rn(v.z, v.w);
            }
            __syncthreads();
#pragma unroll
            for (int kk = 0; kk < 64; kk += 16) {
                wmma::fragment<wmma::matrix_a, 16, 16, 16, __half, wmma::row_major> af[2];
                wmma::fragment<wmma::matrix_b, 16, 16, 16, __half, wmma::col_major> bf[2];
#pragma unroll
                for (int mi = 0; mi < 2; mi++)
                    wmma::load_matrix_sync(af[mi], &sP[(wm * 32 + mi * 16) * LQH + kk], LQH);
#pragma unroll
                for (int ni = 0; ni < 2; ni++)
                    wmma::load_matrix_sync(bf[ni], &sK[(wn * 32 + ni * 16) * LQH + kk], LQH);
#pragma unroll
                for (int mi = 0; mi < 2; mi++)
#pragma unroll
                    for (int ni = 0; ni < 2; ni++)
                        wmma::mma_sync(qacc[mi][ni], af[mi], bf[ni], qacc[mi][ni]);
            }
            __syncthreads();
        }
#pragma unroll
        for (int mi = 0; mi < 2; mi++)
#pragma unroll
            for (int ni = 0; ni < 2; ni++)
                wmma::store_matrix_sync(&sS[(wm * 32 + mi * 16) * LSF + wn * 32 + ni * 16],
                                        qacc[mi][ni], LSF, wmma::mem_row_major);
        __syncthreads();
        {
            int r = tid >> 1, hf = tid & 1;
#pragma unroll
            for (int c = hf * 32; c < hf * 32 + 32; c++)
                sQ[r * LQH + c] = __float2half((sS[r * LSF + c] + bq[col0 + c]) * 0.125f);
        }
    }

    // init O accumulator
    for (int i = tid; i < QTILE * LOF; i += 256) sO[i] = 0.0f;
    float m = -1e30f, l = 0.0f;
    __syncthreads();

    for (int t = 0; t < SEQ / KTILE; t++) {
        const int j0t = t * KTILE;
        // load K,V tiles [128 x 64]
        for (int i = tid; i < KTILE * 8; i += 256) {
            int row = i >> 3, cv = (i & 7) * 8;
            *reinterpret_cast<float4*>(&sK[row * LQH + cv]) =
                *reinterpret_cast<const float4*>(&Kp[(size_t)(j0t + row) * DIMSZ + col0 + cv]);
            *reinterpret_cast<float4*>(&sV[row * LQH + cv]) =
                *reinterpret_cast<const float4*>(&Vp[(size_t)(j0t + row) * DIMSZ + col0 + cv]);
        }
        __syncthreads();

        // S[128x128] = sQ @ sK^T  (scale folded into Q); warps 2(m) x 4(n)
        {
            const int wm = w & 1, wn = w >> 1;
            wmma::fragment<wmma::accumulator, 16, 16, 16, float> sacc[4][2];
#pragma unroll
            for (int mi = 0; mi < 4; mi++)
#pragma unroll
                for (int ni = 0; ni < 2; ni++) wmma::fill_fragment(sacc[mi][ni], 0.0f);
#pragma unroll
            for (int kk = 0; kk < HD; kk += 16) {
                wmma::fragment<wmma::matrix_a, 16, 16, 16, __half, wmma::row_major> af[4];
                wmma::fragment<wmma::matrix_b, 16, 16, 16, __half, wmma::col_major> bf[2];
#pragma unroll
                for (int mi = 0; mi < 4; mi++)
                    wmma::load_matrix_sync(af[mi], &sQ[(wm * 64 + mi * 16) * LQH + kk], LQH);
#pragma unroll
                for (int ni = 0; ni < 2; ni++)
                    wmma::load_matrix_sync(bf[ni], &sK[(wn * 32 + ni * 16) * LQH + kk], LQH);
#pragma unroll
                for (int mi = 0; mi < 4; mi++)
#pragma unroll
                    for (int ni = 0; ni < 2; ni++)
                        wmma::mma_sync(sacc[mi][ni], af[mi], bf[ni], sacc[mi][ni]);
            }
#pragma unroll
            for (int mi = 0; mi < 4; mi++)
#pragma unroll
                for (int ni = 0; ni < 2; ni++)
                    wmma::store_matrix_sync(
                        &sS[(wm * 64 + mi * 16) * LSF + wn * 32 + ni * 16],
                        sacc[mi][ni], LSF, wmma::mem_row_major);
        }
        __syncthreads();

        // online softmax: 2 threads per row (64 cols each), pair-shfl combine
        {
            const int r = tid >> 1, hf = tid & 1;
            const float* Srow = &sS[r * LSF + hf * 64];
            float lmax = -1e30f;
#pragma unroll
            for (int j = 0; j < 64; j++) lmax = fmaxf(lmax, Srow[j]);
            lmax = fmaxf(lmax, __shfl_xor_sync(0xffffffffu, lmax, 1));
            float m_new = fmaxf(m, lmax);
            float alpha = __expf(m - m_new);
            float sum = 0.0f;
            __half* Prow = &sP[r * LPH + hf * 64];
#pragma unroll
            for (int j = 0; j < 64; j += 2) {
                float p0 = __expf(Srow[j]     - m_new);
                float p1 = __expf(Srow[j + 1] - m_new);
                sum += p0 + p1;
                *reinterpret_cast<__half2*>(&Prow[j]) = __floats2half2_rn(p0, p1);
            }
            sum += __shfl_xor_sync(0xffffffffu, sum, 1);
            l = l * alpha + sum;
            m = m_new;
            float* Orow = &sO[r * LOF + hf * 32];
#pragma unroll
            for (int j = 0; j < 32; j += 4) {
                float4 o = *reinterpret_cast<float4*>(&Orow[j]);
                o.x *= alpha; o.y *= alpha; o.z *= alpha; o.w *= alpha;
                *reinterpret_cast<float4*>(&Orow[j]) = o;
            }
        }
        __syncthreads();

        // O[128x64] += P[128x128] @ V[128x64]; warp w owns rows [w*16, w*16+16)
        {
            wmma::fragment<wmma::accumulator, 16, 16, 16, float> oacc[4];
#pragma unroll
            for (int ni = 0; ni < 4; ni++)
                wmma::load_matrix_sync(oacc[ni], &sO[(w * 16) * LOF + ni * 16],
                                       LOF, wmma::mem_row_major);
#pragma unroll
            for (int kk = 0; kk < KTILE; kk += 16) {
                wmma::fragment<wmma::matrix_a, 16, 16, 16, __half, wmma::row_major> af;
                wmma::fragment<wmma::matrix_b, 16, 16, 16, __half, wmma::row_major> bf[4];
                wmma::load_matrix_sync(af, &sP[(w * 16) * LPH + kk], LPH);
#pragma unroll
                for (int ni = 0; ni < 4; ni++)
                    wmma::load_matrix_sync(bf[ni], &sV[kk * LQH + ni * 16], LQH);
#pragma unroll
                for (int ni = 0; ni < 4; ni++)
                    wmma::mma_sync(oacc[ni], af, bf[ni], oacc[ni]);
            }
#pragma unroll
            for (int ni = 0; ni < 4; ni++)
                wmma::store_matrix_sync(&sO[(w * 16) * LOF + ni * 16], oacc[ni],
                                        LOF, wmma::mem_row_major);
        }
        __syncthreads();
    }

    // epilogue: normalize, vectorized half writeback
    {
        const int r = tid >> 1, hf = tid & 1;
        const float inv = 1.0f / l;
        const float* Orow = &sO[r * LOF + hf * 32];
        size_t base = (size_t)(b * SEQ + q0 + r) * DIMSZ + col0 + hf * 32;
#pragma unroll
        for (int j = 0; j < 32; j += 8) {
            union { int4 v; __half2 h[4]; } u;
#pragma unroll
            for (int jj = 0; jj < 4; jj++)
                u.h[jj] = __floats2half2_rn(Orow[j + 2 * jj] * inv,
                                            Orow[j + 2 * jj + 1] * inv);
            *reinterpret_cast<int4*>(&Ap[base + j]) = u.v;
        }
    }
}

// ---------------- copy last 128 A rows into g_tail ----------------
__global__ void copy_tail(const __half* __restrict__ src) {
    int i = blockIdx.x * blockDim.x + threadIdx.x;   // 16384 int4 = 256 KB
    reinterpret_cast<int4*>(g_tail)[i] = reinterpret_cast<const int4*>(src)[i];
}

// ---------------- cascaded output GEMM: out[row0..] = A@Wo^T + bo ----------------
#define OBM 64

__global__ __launch_bounds__(256) void gemm_out(
    const float* __restrict__ W, const float* __restrict__ bias,
    float* __restrict__ out, int row0, int use_tail)
{
    constexpr int K = DIMSZ, NC = DIMSZ;
    const __half* A = use_tail ? g_tail
                               : reinterpret_cast<const __half*>(out) + 4 * 1024 * 1024;
    const int abase = use_tail ? 3968 : 0;

    __shared__ __half As[OBM * LDT];
    __shared__ __half Bs[BN * LDT];
    __shared__ float  stage[8][256];

    const int tid = threadIdx.x;
    const int w = tid >> 5, lane = tid & 31;
    const int wm = w & 1, wn = w >> 1;
    const int m0 = row0 + blockIdx.y * OBM;
    const int n0 = blockIdx.x * BN;

    wmma::fragment<wmma::accumulator, 16, 16, 16, float> acc[2][2];
#pragma unroll
    for (int mi = 0; mi < 2; mi++)
#pragma unroll
        for (int ni = 0; ni < 2; ni++) wmma::fill_fragment(acc[mi][ni], 0.0f);

    for (int k0 = 0; k0 < K; k0 += BK) {
        {
            int row = tid >> 2, cv = (tid & 3) * 8;
            *reinterpret_cast<float4*>(&As[row * LDT + cv]) =
                *reinterpret_cast<const float4*>(&A[(size_t)(m0 + row - abase) * K + k0 + cv]);
        }
#pragma unroll
        for (int it = 0; it < 4; it++) {
            int idx = tid + it * 256;
            int row = idx >> 3, cv = (idx & 7) * 4;
            float4 v = *reinterpret_cast<const float4*>(&W[(size_t)(n0 + row) * K + k0 + cv]);
            __half* dst = &Bs[row * LDT + cv];
            *reinterpret_cast<__half2*>(dst)     = __floats2half2_rn(v.x, v.y);
            *reinterpret_cast<__half2*>(dst + 2) = __floats2half2_rn(v.z, v.w);
        }
        __syncthreads();
#pragma unroll
        for (int kk = 0; kk < BK; kk += 16) {
            wmma::fragment<wmma::matrix_a, 16, 16, 16, __half, wmma::row_major> af[2];
            wmma::fragment<wmma::matrix_b, 16, 16, 16, __half, wmma::col_major> bf[2];
#pragma unroll
            for (int mi = 0; mi < 2; mi++)
                wmma::load_matrix_sync(af[mi], &As[(wm * 32 + mi * 16) * LDT + kk], LDT);
#pragma unroll
            for (int ni = 0; ni < 2; ni++)
                wmma::load_matrix_sync(bf[ni], &Bs[(wn * 32 + ni * 16) * LDT + kk], LDT);
#pragma unroll
            for (int mi = 0; mi < 2; mi++)
#pragma unroll
                for (int ni = 0; ni < 2; ni++)
                    wmma::mma_sync(acc[mi][ni], af[mi], bf[ni], acc[mi][ni]);
        }
        __syncthreads();
    }
#pragma unroll
    for (int mi = 0; mi < 2; mi++)
#pragma unroll
        for (int ni = 0; ni < 2; ni++) {
            wmma::store_matrix_sync(&stage[w][0], acc[mi][ni], 16, wmma::mem_row_major);
            __syncwarp();
            int grow0 = m0 + wm * 32 + mi * 16;
            int gcol0 = n0 + wn * 32 + ni * 16;
#pragma unroll
            for (int e = lane; e < 256; e += 32) {
                int r = e >> 4, c = e & 15;
                out[(size_t)(grow0 + r) * NC + gcol0 + c] = stage[w][e] + bias[gcol0 + c];
            }
            __syncwarp();
        }
}

// ---------------- launch ----------------
extern "C" void kernel_launch(void* const* d_in, const int* in_sizes, int n_in,
                              void* d_out, int out_size) {
    const float* query = (const float*)d_in[0];
    const float* key   = (const float*)d_in[1];
    const float* value = (const float*)d_in[2];
    const float* Wq    = (const float*)d_in[3];
    const float* bq    = (const float*)d_in[4];
    const float* Wk    = (const float*)d_in[5];
    const float* bk    = (const float*)d_in[6];
    const float* Wv    = (const float*)d_in[7];
    const float* bv    = (const float*)d_in[8];
    const float* Wo    = (const float*)d_in[9];
    const float* bo    = (const float*)d_in[10];
    float* out = (float*)d_out;
    __half* dbase = (__half*)d_out;

    cudaFuncSetAttribute(attn_kernel, cudaFuncAttributeMaxDynamicSharedMemorySize, ATT_SMEM);

    dim3 pgrid(DIMSZ / BN, SEQ / BM, 2);         // (8, 16, 2): K and V fused
    dim3 agrid(SEQ / QTILE, HEADS);              // (16, 16)

    // batch 0
    gemm_proj_kv<<<pgrid, 256>>>(key, value, Wk, bk, Wv, bv,
                                 dbase, dbase + 2 * 1024 * 1024);
    attn_kernel<<<agrid, 256, ATT_SMEM>>>(query, Wq, bq, dbase, 0);

    // batch 1 (K/V overwrite batch 0's, A goes to [12:16MB))
    gemm_proj_kv<<<pgrid, 256>>>(key + (size_t)SEQ * DIMSZ, value + (size_t)SEQ * DIMSZ,
                                 Wk, bk, Wv, bv, dbase, dbase + 2 * 1024 * 1024);
    attn_kernel<<<agrid, 256, ATT_SMEM>>>(query, Wq, bq, dbase, 1);

    // stash last 128 A rows, then cascaded in-place output GEMM
    copy_tail<<<64, 256>>>(dbase + 4 * 1024 * 1024 + (size_t)3968 * DIMSZ);

    const int seg[6] = {0, 2048, 3072, 3584, 3840, 3968};
    for (int i = 0; i < 5; i++) {
        dim3 g(DIMSZ / BN, (seg[i + 1] - seg[i]) / OBM);
        gemm_out<<<g, 256>>>(Wo, bo, out, seg[i], 0);
    }
    gemm_out<<<dim3(DIMSZ / BN, 2), 256>>>(Wo, bo, out, 3968, 1);
}